// round 2
// baseline (speedup 1.0000x reference)
#include <cuda_runtime.h>
#include <cstdint>
#include <cstddef>

// Problem constants
#define TT 1024
#define BB 512
#define VV 29
#define HH 64
#define GG 256          // 4*H
#define RR 4            // batch rows per block
#define NBLK 128        // 512 / 4
#define SOS_BIT (1u << 27)

// ---------------------------------------------------------------------------
// Device scratch (allocation-free rule: __device__ globals)
// ---------------------------------------------------------------------------
__device__ float g_y1[(size_t)TT * BB * HH];   // encoder layer0 output sequence (134 MB)
__device__ float g_h1[BB * HH];                // encoder layer1 final h
__device__ float g_c1[BB * HH];                // encoder layer1 final c
__device__ unsigned g_mask[TT + 1];            // decoder one-hot-union masks per step
__device__ unsigned g_bar_count;
__device__ unsigned g_bar_gen;

__device__ __forceinline__ float sigf(float x) { return 1.0f / (1.0f + expf(-x)); }

// ---------------------------------------------------------------------------
// Init: reset masks + barrier state every launch (deterministic replays)
// ---------------------------------------------------------------------------
__global__ void init_kernel() {
    int i = blockIdx.x * blockDim.x + threadIdx.x;
    if (i <= TT) g_mask[i] = (i == 0) ? SOS_BIT : 0u;
    if (i == 0) { g_bar_count = 0u; g_bar_gen = 0u; }
}

// ---------------------------------------------------------------------------
// Encoder layer 0: input V=29 -> H=64. 128 blocks x 4 rows, 256 threads.
// Thread t owns gate row t (Wih row: 29 pad 32, Whh row: 64) in registers.
// ---------------------------------------------------------------------------
__global__ __launch_bounds__(256, 1) void enc0_kernel(
    const float* __restrict__ x_seq,
    const float* __restrict__ Wih, const float* __restrict__ Whh,
    const float* __restrict__ bih, const float* __restrict__ bhh)
{
    __shared__ __align__(16) float xs[RR][32];
    __shared__ __align__(16) float hs[RR][HH];
    __shared__ float gs[RR][GG];

    const int tid = threadIdx.x;
    const int r0  = blockIdx.x * RR;

    float wih[32];
#pragma unroll
    for (int k = 0; k < 32; k++) wih[k] = (k < VV) ? Wih[tid * VV + k] : 0.0f;
    float whh[HH];
#pragma unroll
    for (int k = 0; k < HH; k++) whh[k] = Whh[tid * HH + k];
    const float bias = bih[tid] + bhh[tid];

    const int prow = tid >> 6, pj = tid & 63;
    hs[prow][pj] = 0.0f;
    if (tid < RR * 3) xs[tid / 3][VV + tid % 3] = 0.0f;   // zero the pad (avoid NaN*0)
    float c_own = 0.0f;
    __syncthreads();

    for (int step = 0; step < TT; step++) {
        if (tid < RR * VV) {
            int row = tid / VV, v = tid % VV;
            xs[row][v] = x_seq[((size_t)step * BB + r0 + row) * VV + v];
        }
        __syncthreads();   // xs + hs ready; also orders prev pointwise before gates

#pragma unroll
        for (int row = 0; row < RR; row++) {
            const float4* xp = (const float4*)xs[row];
            const float4* hp = (const float4*)hs[row];
            float a = bias;
#pragma unroll
            for (int q = 0; q < 8; q++) {
                float4 xv = xp[q];
                a += wih[4*q+0]*xv.x; a += wih[4*q+1]*xv.y;
                a += wih[4*q+2]*xv.z; a += wih[4*q+3]*xv.w;
            }
#pragma unroll
            for (int q = 0; q < 16; q++) {
                float4 hv = hp[q];
                a += whh[4*q+0]*hv.x; a += whh[4*q+1]*hv.y;
                a += whh[4*q+2]*hv.z; a += whh[4*q+3]*hv.w;
            }
            gs[row][tid] = a;
        }
        __syncthreads();   // gates ready

        {
            float gi = gs[prow][pj];
            float gf = gs[prow][64 + pj];
            float gc = gs[prow][128 + pj];
            float go = gs[prow][192 + pj];
            c_own = sigf(gf) * c_own + sigf(gi) * tanhf(gc);
            float h = sigf(go) * tanhf(c_own);
            hs[prow][pj] = h;
            g_y1[((size_t)step * BB + (r0 + prow)) * HH + pj] = h;
        }
        // no third sync needed: next iter's first sync orders pointwise vs gates
    }
}

// ---------------------------------------------------------------------------
// Encoder layer 1: H=64 -> H=64, input from g_y1. Writes final (h, c).
// ---------------------------------------------------------------------------
__global__ __launch_bounds__(256, 1) void enc1_kernel(
    const float* __restrict__ Wih, const float* __restrict__ Whh,
    const float* __restrict__ bih, const float* __restrict__ bhh)
{
    __shared__ __align__(16) float ys[RR][HH];
    __shared__ __align__(16) float hs[RR][HH];
    __shared__ float gs[RR][GG];

    const int tid = threadIdx.x;
    const int r0  = blockIdx.x * RR;

    float wih[HH];
#pragma unroll
    for (int k = 0; k < HH; k++) wih[k] = Wih[tid * HH + k];
    float whh[HH];
#pragma unroll
    for (int k = 0; k < HH; k++) whh[k] = Whh[tid * HH + k];
    const float bias = bih[tid] + bhh[tid];

    const int prow = tid >> 6, pj = tid & 63;
    hs[prow][pj] = 0.0f;
    float c_own = 0.0f;
    __syncthreads();

    for (int step = 0; step < TT; step++) {
        ys[prow][pj] = g_y1[((size_t)step * BB + r0 + prow) * HH + pj];
        __syncthreads();

#pragma unroll
        for (int row = 0; row < RR; row++) {
            const float4* xp = (const float4*)ys[row];
            const float4* hp = (const float4*)hs[row];
            float a = bias;
#pragma unroll
            for (int q = 0; q < 16; q++) {
                float4 xv = xp[q];
                a += wih[4*q+0]*xv.x; a += wih[4*q+1]*xv.y;
                a += wih[4*q+2]*xv.z; a += wih[4*q+3]*xv.w;
            }
#pragma unroll
            for (int q = 0; q < 16; q++) {
                float4 hv = hp[q];
                a += whh[4*q+0]*hv.x; a += whh[4*q+1]*hv.y;
                a += whh[4*q+2]*hv.z; a += whh[4*q+3]*hv.w;
            }
            gs[row][tid] = a;
        }
        __syncthreads();

        {
            float gi = gs[prow][pj];
            float gf = gs[prow][64 + pj];
            float gc = gs[prow][128 + pj];
            float go = gs[prow][192 + pj];
            c_own = sigf(gf) * c_own + sigf(gi) * tanhf(gc);
            float h = sigf(go) * tanhf(c_own);
            hs[prow][pj] = h;
            if (step == TT - 1) {
                g_h1[(size_t)(r0 + prow) * HH + pj] = h;
                g_c1[(size_t)(r0 + prow) * HH + pj] = c_own;
            }
        }
    }
}

// ---------------------------------------------------------------------------
// Decoder: persistent kernel, 128 blocks x 512 threads, grid barrier per step.
// Gate g handled by thread pair (2g, 2g+1); each owns a 32-wide k-slice of
// d1_Whh / d2_Wih / d2_Whh in registers (96 regs). let-contribution computed
// as mask-predicated column sums of d1_Wih (transposed copy in smem).
// ---------------------------------------------------------------------------
__device__ __forceinline__ void grid_barrier() {
    __syncthreads();
    if (threadIdx.x == 0) {
        __threadfence();
        unsigned gen = *((volatile unsigned*)&g_bar_gen);
        if (atomicAdd(&g_bar_count, 1u) == (unsigned)(NBLK - 1)) {
            atomicExch(&g_bar_count, 0u);
            __threadfence();
            *((volatile unsigned*)&g_bar_gen) = gen + 1u;
        } else {
            while (*((volatile unsigned*)&g_bar_gen) == gen) { }
        }
        __threadfence();
    }
    __syncthreads();
}

__global__ __launch_bounds__(512, 1) void dec_kernel(
    const float* __restrict__ d1_Wih, const float* __restrict__ d1_Whh,
    const float* __restrict__ d1_bih, const float* __restrict__ d1_bhh,
    const float* __restrict__ d2_Wih, const float* __restrict__ d2_Whh,
    const float* __restrict__ d2_bih, const float* __restrict__ d2_bhh,
    const float* __restrict__ cls_W, const float* __restrict__ cls_b,
    float* __restrict__ out)
{
    extern __shared__ float dsm[];
    float*    wih1T = dsm;                  // [29][256]  7424
    float*    clsT  = wih1T + VV * GG;      // [64][29]   1856
    float*    clsb  = clsT + HH * VV;       // [32]
    float*    letc  = clsb + 32;            // [256]
    float*    h1s   = letc + GG;            // [4][64]   (16B aligned)
    float*    h2s   = h1s + RR * HH;        // [4][64]
    float*    g1s   = h2s + RR * HH;        // [4][256]
    float*    g2s   = g1s + RR * GG;        // [4][256]
    float*    ps    = g2s + RR * GG;        // [4][32]
    unsigned* smask = (unsigned*)(ps + RR * 32);

    const int tid  = threadIdx.x;
    const int g    = tid >> 1;
    const int half = tid & 1;
    const int ko   = half * 32;
    const int r0   = blockIdx.x * RR;

    float whh1[32], wih2[32], whh2[32];
#pragma unroll
    for (int k = 0; k < 32; k++) whh1[k] = d1_Whh[g * HH + ko + k];
#pragma unroll
    for (int k = 0; k < 32; k++) wih2[k] = d2_Wih[g * HH + ko + k];
#pragma unroll
    for (int k = 0; k < 32; k++) whh2[k] = d2_Whh[g * HH + ko + k];
    const float bias1 = d1_bih[g] + d1_bhh[g];
    const float bias2 = d2_bih[g] + d2_bhh[g];

    for (int i = tid; i < VV * GG; i += 512) {
        int gg = i / VV, j = i % VV;
        wih1T[j * GG + gg] = d1_Wih[i];
    }
    for (int i = tid; i < VV * HH; i += 512) {
        int v = i / HH, k = i % HH;
        clsT[k * VV + v] = cls_W[i];
    }
    if (tid < VV) clsb[tid] = cls_b[tid];

    float c_own;
    if (tid < 256) {
        int row = tid >> 6, j = tid & 63;
        h1s[tid] = g_h1[(size_t)(r0 + row) * HH + j];
        c_own    = g_c1[(size_t)(r0 + row) * HH + j];
        h2s[tid] = 0.0f;
    } else {
        c_own = 0.0f;
    }
    __syncthreads();

    for (int step = 0; step < TT; step++) {
        const unsigned mask = __ldcg(g_mask + step);
        if (tid == 0) *smask = 0u;

        // let-contribution: column sums of d1_Wih over set mask bits
        if (tid < 256) {
            float a = 0.0f;
#pragma unroll
            for (int j = 0; j < VV; j++)
                if (mask & (1u << j)) a += wih1T[j * GG + tid];
            letc[tid] = a;
        }
        __syncthreads();

        // cell1 gates: letc + h1 @ d1_Whh.T + bias
#pragma unroll
        for (int row = 0; row < RR; row++) {
            const float4* hp = (const float4*)(h1s + row * HH + ko);
            float a = half ? 0.0f : (bias1 + letc[g]);
#pragma unroll
            for (int q = 0; q < 8; q++) {
                float4 hv = hp[q];
                a += whh1[4*q+0]*hv.x; a += whh1[4*q+1]*hv.y;
                a += whh1[4*q+2]*hv.z; a += whh1[4*q+3]*hv.w;
            }
            a += __shfl_xor_sync(0xffffffffu, a, 1);
            if (!half) g1s[row * GG + g] = a;
        }
        __syncthreads();

        // cell1 pointwise (threads 0..255 own c1)
        if (tid < 256) {
            int row = tid >> 6, j = tid & 63;
            float gi = g1s[row * GG + j];
            float gf = g1s[row * GG + 64 + j];
            float gc = g1s[row * GG + 128 + j];
            float go = g1s[row * GG + 192 + j];
            c_own = sigf(gf) * c_own + sigf(gi) * tanhf(gc);
            h1s[tid] = sigf(go) * tanhf(c_own);
        }
        __syncthreads();

        // cell2 gates: h1_new @ d2_Wih.T + h2 @ d2_Whh.T + bias
#pragma unroll
        for (int row = 0; row < RR; row++) {
            const float4* hp1 = (const float4*)(h1s + row * HH + ko);
            const float4* hp2 = (const float4*)(h2s + row * HH + ko);
            float a = half ? 0.0f : bias2;
#pragma unroll
            for (int q = 0; q < 8; q++) {
                float4 hv = hp1[q];
                a += wih2[4*q+0]*hv.x; a += wih2[4*q+1]*hv.y;
                a += wih2[4*q+2]*hv.z; a += wih2[4*q+3]*hv.w;
            }
#pragma unroll
            for (int q = 0; q < 8; q++) {
                float4 hv = hp2[q];
                a += whh2[4*q+0]*hv.x; a += whh2[4*q+1]*hv.y;
                a += whh2[4*q+2]*hv.z; a += whh2[4*q+3]*hv.w;
            }
            a += __shfl_xor_sync(0xffffffffu, a, 1);
            if (!half) g2s[row * GG + g] = a;
        }
        __syncthreads();

        // cell2 pointwise (threads 256..511 own c2)
        if (tid >= 256) {
            int t2 = tid - 256;
            int row = t2 >> 6, j = t2 & 63;
            float gi = g2s[row * GG + j];
            float gf = g2s[row * GG + 64 + j];
            float gc = g2s[row * GG + 128 + j];
            float go = g2s[row * GG + 192 + j];
            c_own = sigf(gf) * c_own + sigf(gi) * tanhf(gc);
            h2s[t2] = sigf(go) * tanhf(c_own);
        }
        __syncthreads();

        // classifier: pred[row][v] = h2 . cls_W[v] + cls_b[v]; pairs split k
        if (tid < 256) {
            int p = tid >> 1;
            bool valid = (p < RR * VV);
            int row = valid ? (p / VV) : 0;
            int v   = valid ? (p % VV) : 0;
            float a = 0.0f;
            if (valid) {
                const float* h2r = h2s + row * HH + ko;
                a = half ? 0.0f : clsb[v];
#pragma unroll
                for (int k = 0; k < 32; k++)
                    a += h2r[k] * clsT[(ko + k) * VV + v];
            }
            a += __shfl_xor_sync(0xffffffffu, a, 1);
            if (valid && !half) {
                ps[row * 32 + v] = a;
                out[((size_t)step * BB + r0 + row) * VV + v] = a;
            }
        }
        __syncthreads();

        // per-row argmax (first-occurrence max, matching jnp.argmax), OR into mask
        if (tid < RR) {
            float best = ps[tid * 32];
            int bi = 0;
#pragma unroll
            for (int v = 1; v < VV; v++) {
                float x = ps[tid * 32 + v];
                if (x > best) { best = x; bi = v; }
            }
            atomicOr(smask, 1u << bi);
        }
        __syncthreads();
        if (tid == 0) atomicOr(g_mask + step + 1, *smask);

        grid_barrier();
    }
}

// ---------------------------------------------------------------------------
// Launch
// ---------------------------------------------------------------------------
extern "C" void kernel_launch(void* const* d_in, const int* in_sizes, int n_in,
                              void* d_out, int out_size)
{
    const float* input_seq = (const float*)d_in[0];
    const float* enc_Wih0  = (const float*)d_in[1];
    const float* enc_Whh0  = (const float*)d_in[2];
    const float* enc_bih0  = (const float*)d_in[3];
    const float* enc_bhh0  = (const float*)d_in[4];
    const float* enc_Wih1  = (const float*)d_in[5];
    const float* enc_Whh1  = (const float*)d_in[6];
    const float* enc_bih1  = (const float*)d_in[7];
    const float* enc_bhh1  = (const float*)d_in[8];
    const float* d1_Wih    = (const float*)d_in[9];
    const float* d1_Whh    = (const float*)d_in[10];
    const float* d1_bih    = (const float*)d_in[11];
    const float* d1_bhh    = (const float*)d_in[12];
    const float* d2_Wih    = (const float*)d_in[13];
    const float* d2_Whh    = (const float*)d_in[14];
    const float* d2_bih    = (const float*)d_in[15];
    const float* d2_bhh    = (const float*)d_in[16];
    const float* cls_W     = (const float*)d_in[17];
    const float* cls_b     = (const float*)d_in[18];
    float* out = (float*)d_out;

    const int dec_smem = (VV*GG + HH*VV + 32 + GG + RR*HH*2 + RR*GG*2 + RR*32) * 4 + 16;
    cudaFuncSetAttribute(dec_kernel, cudaFuncAttributeMaxDynamicSharedMemorySize, dec_smem);

    init_kernel<<<3, 512>>>();
    enc0_kernel<<<NBLK, 256>>>(input_seq, enc_Wih0, enc_Whh0, enc_bih0, enc_bhh0);
    enc1_kernel<<<NBLK, 256>>>(enc_Wih1, enc_Whh1, enc_bih1, enc_bhh1);
    dec_kernel<<<NBLK, 512, dec_smem>>>(d1_Wih, d1_Whh, d1_bih, d1_bhh,
                                        d2_Wih, d2_Whh, d2_bih, d2_bhh,
                                        cls_W, cls_b, out);
}

// round 7
// speedup vs baseline: 1.1473x; 1.1473x over previous
#include <cuda_runtime.h>
#include <cstdint>
#include <cstddef>
#include <math_constants.h>

#define TT 1024
#define BB 512
#define VV 29
#define HH 64
#define GG 256          // 4*H
#define RR 4            // batch rows per block
#define NBLK 128        // 512 / 4
#define SOS_BIT (1u << 27)

// ---------------------------------------------------------------------------
// Device scratch
// ---------------------------------------------------------------------------
__device__ float g_y1[(size_t)TT * BB * HH];   // encoder layer0 output (134 MB)
__device__ float g_h1[BB * HH];
__device__ float g_c1[BB * HH];
__device__ unsigned g_mask[TT + 1];            // per-step one-hot-union masks
__device__ unsigned g_cnt[TT + 1];             // per-step release counters

typedef unsigned long long u64;

// ---------------------------------------------------------------------------
// f32x2 packed-FMA helpers (FFMA2 — PTX-only form, 2 MACs per issue slot)
// ---------------------------------------------------------------------------
__device__ __forceinline__ u64 ffma2(u64 a, u64 b, u64 c) {
    u64 d; asm("fma.rn.f32x2 %0, %1, %2, %3;" : "=l"(d) : "l"(a), "l"(b), "l"(c));
    return d;
}
__device__ __forceinline__ u64 fadd2(u64 a, u64 b) {
    u64 d; asm("add.rn.f32x2 %0, %1, %2;" : "=l"(d) : "l"(a), "l"(b));
    return d;
}
__device__ __forceinline__ u64 pk2(float lo, float hi) {
    u64 d; asm("mov.b64 %0, {%1, %2};" : "=l"(d) : "f"(lo), "f"(hi));
    return d;
}
__device__ __forceinline__ float f2sum(u64 a) {
    float lo, hi; asm("mov.b64 {%0, %1}, %2;" : "=f"(lo), "=f"(hi) : "l"(a));
    return lo + hi;
}
__device__ __forceinline__ unsigned ld_acq(const unsigned* p) {
    unsigned v;
    asm volatile("ld.global.acquire.gpu.u32 %0, [%1];" : "=r"(v) : "l"(p) : "memory");
    return v;
}
__device__ __forceinline__ float sigf(float x) { return 1.0f / (1.0f + expf(-x)); }

// ---------------------------------------------------------------------------
// Init: reset masks + counters (deterministic graph replays)
// ---------------------------------------------------------------------------
__global__ void init_kernel() {
    int i = blockIdx.x * blockDim.x + threadIdx.x;
    if (i <= TT) {
        g_mask[i] = (i == 0) ? SOS_BIT : 0u;
        g_cnt[i]  = (i == 0) ? (unsigned)NBLK : 0u;
    }
}

// ---------------------------------------------------------------------------
// Encoder layer 0: V=29 -> H=64. 128 blocks x 512 threads.
// Gate g handled by pair (2g, 2g+1); each holds a k-slice in regs (f32x2).
// ---------------------------------------------------------------------------
__global__ __launch_bounds__(512, 1) void enc0_kernel(
    const float* __restrict__ x_seq,
    const float* __restrict__ Wih, const float* __restrict__ Whh,
    const float* __restrict__ bih, const float* __restrict__ bhh)
{
    __shared__ __align__(16) float xs[2][RR][32];
    __shared__ __align__(16) float hs[RR][HH];
    __shared__ float gs[RR][GG];

    const int tid  = threadIdx.x;
    const int g    = tid >> 1;
    const int half = tid & 1;
    const int kx0  = half * 16;
    const int kh0  = half * 32;
    const int r0   = blockIdx.x * RR;

    u64 wx[8], wh[16];
#pragma unroll
    for (int q = 0; q < 8; q++) {
        int k = kx0 + 2 * q;
        float a = (k < VV)     ? Wih[g * VV + k]     : 0.0f;
        float b = (k + 1 < VV) ? Wih[g * VV + k + 1] : 0.0f;
        wx[q] = pk2(a, b);
    }
#pragma unroll
    for (int q = 0; q < 16; q++)
        wh[q] = pk2(Whh[g * HH + kh0 + 2 * q], Whh[g * HH + kh0 + 2 * q + 1]);
    const float bias = half ? 0.0f : (bih[g] + bhh[g]);

    if (tid < 256) hs[tid >> 6][tid & 63] = 0.0f;
    if (tid < 2 * RR * 3) {     // zero x pads in both buffers
        int b = tid / (RR * 3), r = (tid / 3) % RR, k = VV + tid % 3;
        xs[b][r][k] = 0.0f;
    }
    if (tid < RR * VV) {
        int row = tid / VV, v = tid % VV;
        xs[0][row][v] = x_seq[((size_t)0 * BB + r0 + row) * VV + v];
    }
    float c = 0.0f;
    __syncthreads();

    int cur = 0;
    for (int step = 0; step < TT; step++) {
#pragma unroll
        for (int row = 0; row < RR; row++) {
            const u64* xp = (const u64*)&xs[cur][row][kx0];
            const u64* hp = (const u64*)&hs[row][kh0];
            u64 a0 = 0ull, a1 = 0ull;
#pragma unroll
            for (int q = 0; q < 8; q += 2) {
                a0 = ffma2(wx[q],     xp[q],     a0);
                a1 = ffma2(wx[q + 1], xp[q + 1], a1);
            }
#pragma unroll
            for (int q = 0; q < 16; q += 2) {
                a0 = ffma2(wh[q],     hp[q],     a0);
                a1 = ffma2(wh[q + 1], hp[q + 1], a1);
            }
            float s = f2sum(fadd2(a0, a1)) + bias;
            s += __shfl_xor_sync(0xffffffffu, s, 1);
            if (!half) gs[row][g] = s;
        }
        if (step + 1 < TT && tid < RR * VV) {
            int row = tid / VV, v = tid % VV;
            xs[cur ^ 1][row][v] = x_seq[((size_t)(step + 1) * BB + r0 + row) * VV + v];
        }
        __syncthreads();

        if (tid < 256) {
            int row = tid >> 6, j = tid & 63;
            float gi = gs[row][j];
            float gf = gs[row][64 + j];
            float gc = gs[row][128 + j];
            float go = gs[row][192 + j];
            c = sigf(gf) * c + sigf(gi) * tanhf(gc);
            float h = sigf(go) * tanhf(c);
            hs[row][j] = h;
            g_y1[((size_t)step * BB + r0 + row) * HH + j] = h;
        }
        __syncthreads();
        cur ^= 1;
    }
}

// ---------------------------------------------------------------------------
// Encoder layer 1: H=64 -> H=64. Same skeleton, input from g_y1.
// ---------------------------------------------------------------------------
__global__ __launch_bounds__(512, 1) void enc1_kernel(
    const float* __restrict__ Wih, const float* __restrict__ Whh,
    const float* __restrict__ bih, const float* __restrict__ bhh)
{
    __shared__ __align__(16) float ys[2][RR * HH];
    __shared__ __align__(16) float hs[RR][HH];
    __shared__ float gs[RR][GG];

    const int tid  = threadIdx.x;
    const int g    = tid >> 1;
    const int half = tid & 1;
    const int kh0  = half * 32;
    const int r0   = blockIdx.x * RR;

    u64 wx[16], wh[16];
#pragma unroll
    for (int q = 0; q < 16; q++) {
        wx[q] = pk2(Wih[g * HH + kh0 + 2 * q], Wih[g * HH + kh0 + 2 * q + 1]);
        wh[q] = pk2(Whh[g * HH + kh0 + 2 * q], Whh[g * HH + kh0 + 2 * q + 1]);
    }
    const float bias = half ? 0.0f : (bih[g] + bhh[g]);

    if (tid < 256) hs[tid >> 6][tid & 63] = 0.0f;
    if (tid < 64)
        ((float4*)ys[0])[tid] = ((const float4*)(g_y1 + (size_t)r0 * HH))[tid];
    float c = 0.0f;
    __syncthreads();

    int cur = 0;
    for (int step = 0; step < TT; step++) {
#pragma unroll
        for (int row = 0; row < RR; row++) {
            const u64* xp = (const u64*)&ys[cur][row * HH + kh0];
            const u64* hp = (const u64*)&hs[row][kh0];
            u64 a0 = 0ull, a1 = 0ull;
#pragma unroll
            for (int q = 0; q < 16; q += 2) {
                a0 = ffma2(wx[q],     xp[q],     a0);
                a1 = ffma2(wx[q + 1], xp[q + 1], a1);
            }
#pragma unroll
            for (int q = 0; q < 16; q += 2) {
                a0 = ffma2(wh[q],     hp[q],     a0);
                a1 = ffma2(wh[q + 1], hp[q + 1], a1);
            }
            float s = f2sum(fadd2(a0, a1)) + bias;
            s += __shfl_xor_sync(0xffffffffu, s, 1);
            if (!half) gs[row][g] = s;
        }
        if (step + 1 < TT && tid < 64)
            ((float4*)ys[cur ^ 1])[tid] =
                ((const float4*)(g_y1 + (size_t)(step + 1) * BB * HH + (size_t)r0 * HH))[tid];
        __syncthreads();

        if (tid < 256) {
            int row = tid >> 6, j = tid & 63;
            float gi = gs[row][j];
            float gf = gs[row][64 + j];
            float gc = gs[row][128 + j];
            float go = gs[row][192 + j];
            c = sigf(gf) * c + sigf(gi) * tanhf(gc);
            float h = sigf(go) * tanhf(c);
            hs[row][j] = h;
            if (step == TT - 1) {
                g_h1[(size_t)r0 * HH + tid] = h;
                g_c1[(size_t)r0 * HH + tid] = c;
            }
        }
        __syncthreads();
        cur ^= 1;
    }
}

// ---------------------------------------------------------------------------
// Decoder: persistent, 128 blocks x 512 threads.
// Pair (2g, 2g+1) owns gate g for BOTH cells (k-split halves) -> full 256-gate
// coverage (fixes R3's 128-gate bug). c1 owned by tid<256, c2 by tid>=256.
// h2*Whh2 dot is computed BEFORE the per-step spin to hide release latency.
// ---------------------------------------------------------------------------
__global__ __launch_bounds__(512, 1) void dec_kernel(
    const float* __restrict__ d1_Wih, const float* __restrict__ d1_Whh,
    const float* __restrict__ d1_bih, const float* __restrict__ d1_bhh,
    const float* __restrict__ d2_Wih, const float* __restrict__ d2_Whh,
    const float* __restrict__ d2_bih, const float* __restrict__ d2_bhh,
    const float* __restrict__ cls_W, const float* __restrict__ cls_b,
    float* __restrict__ out)
{
    __shared__ float wih1T[VV * GG];                 // [j][g] letc table
    __shared__ __align__(16) u64 clsP[32 * 32];      // [kpair][v] packed cls weights
    __shared__ __align__(16) float h1s[RR * HH];
    __shared__ __align__(16) float h2s[RR * HH];
    __shared__ float g1s[RR * GG];
    __shared__ float g2s[RR * GG];
    __shared__ __align__(16) float ps[RR * 32];
    __shared__ float clsb[32];

    const int tid  = threadIdx.x;
    const int g    = tid >> 1;
    const int half = tid & 1;
    const int ko   = half * 32;
    const int lane = tid & 31;
    const int r0   = blockIdx.x * RR;

    u64 whh1[16], wih2[16], whh2[16];
#pragma unroll
    for (int q = 0; q < 16; q++) {
        whh1[q] = pk2(d1_Whh[g * HH + ko + 2 * q], d1_Whh[g * HH + ko + 2 * q + 1]);
        wih2[q] = pk2(d2_Wih[g * HH + ko + 2 * q], d2_Wih[g * HH + ko + 2 * q + 1]);
        whh2[q] = pk2(d2_Whh[g * HH + ko + 2 * q], d2_Whh[g * HH + ko + 2 * q + 1]);
    }
    const float bias1 = half ? 0.0f : (d1_bih[g] + d1_bhh[g]);
    const float bias2 = half ? 0.0f : (d2_bih[g] + d2_bhh[g]);

    for (int i = tid; i < VV * GG; i += 512)
        wih1T[(i % VV) * GG + (i / VV)] = d1_Wih[i];
    for (int i = tid; i < VV * 32; i += 512) {
        int v = i >> 5, kk = i & 31;
        clsP[kk * 32 + v] = pk2(cls_W[v * HH + 2 * kk], cls_W[v * HH + 2 * kk + 1]);
    }
    if (tid < VV) clsb[tid] = cls_b[tid];
    if (tid < RR * 3) ps[(tid / 3) * 32 + VV + tid % 3] = -CUDART_INF_F;

    float c;
    if (tid < 256) {
        h1s[tid] = g_h1[(size_t)r0 * HH + tid];
        c        = g_c1[(size_t)r0 * HH + tid];
        h2s[tid] = 0.0f;
    } else {
        c = 0.0f;
    }
    __syncthreads();

    // letc j-range split across the pair (folds into the gate shfl-reduce)
    const int j0 = half ? 15 : 0;
    const int j1 = half ? VV : 15;

    for (int step = 0; step < TT; step++) {
        // ---- pre-phase: mask-independent h2 * Whh2 dot (hides spin) ----
        u64 acc2[RR];
#pragma unroll
        for (int row = 0; row < RR; row++) {
            const u64* hp = (const u64*)&h2s[row * HH + ko];
            u64 a0 = 0ull, a1 = 0ull;
#pragma unroll
            for (int q = 0; q < 16; q += 2) {
                a0 = ffma2(whh2[q],     hp[q],     a0);
                a1 = ffma2(whh2[q + 1], hp[q + 1], a1);
            }
            acc2[row] = fadd2(a0, a1);
        }

        // ---- acquire this step's mask (lane 0 of each warp spins) ----
        unsigned mask;
        if (lane == 0) {
            while (ld_acq(&g_cnt[step]) < (unsigned)NBLK) { }
            mask = ld_acq(&g_mask[step]);
        }
        mask = __shfl_sync(0xffffffffu, mask, 0);

        // ---- cell1 gates: (letc-half + bias) + h1 * Whh1 (pair k-split) ----
        float ls = bias1;
        for (int j = j0; j < j1; j++)
            if ((mask >> j) & 1u) ls += wih1T[j * GG + g];
#pragma unroll
        for (int row = 0; row < RR; row++) {
            const u64* hp = (const u64*)&h1s[row * HH + ko];
            u64 a0 = 0ull, a1 = 0ull;
#pragma unroll
            for (int q = 0; q < 16; q += 2) {
                a0 = ffma2(whh1[q],     hp[q],     a0);
                a1 = ffma2(whh1[q + 1], hp[q + 1], a1);
            }
            float s = f2sum(fadd2(a0, a1)) + ls;
            s += __shfl_xor_sync(0xffffffffu, s, 1);
            if (!half) g1s[row * GG + g] = s;
        }
        __syncthreads();

        // ---- cell1 pointwise (tid<256 owns c1) ----
        if (tid < 256) {
            int row = tid >> 6, j = tid & 63;
            float gi = g1s[row * GG + j];
            float gf = g1s[row * GG + 64 + j];
            float gc = g1s[row * GG + 128 + j];
            float go = g1s[row * GG + 192 + j];
            c = sigf(gf) * c + sigf(gi) * tanhf(gc);
            h1s[tid] = sigf(go) * tanhf(c);
        }
        __syncthreads();

        // ---- cell2 gates: h1_new * Wih2 + precomputed h2-dot ----
#pragma unroll
        for (int row = 0; row < RR; row++) {
            const u64* hp = (const u64*)&h1s[row * HH + ko];
            u64 a = acc2[row];
#pragma unroll
            for (int q = 0; q < 16; q++)
                a = ffma2(wih2[q], hp[q], a);
            float s = f2sum(a) + bias2;
            s += __shfl_xor_sync(0xffffffffu, s, 1);
            if (!half) g2s[row * GG + g] = s;
        }
        __syncthreads();

        // ---- cell2 pointwise (tid>=256 owns c2) ----
        if (tid >= 256) {
            int t2 = tid - 256;
            int row = t2 >> 6, j = t2 & 63;
            float gi = g2s[row * GG + j];
            float gf = g2s[row * GG + 64 + j];
            float gc = g2s[row * GG + 128 + j];
            float go = g2s[row * GG + 192 + j];
            c = sigf(gf) * c + sigf(gi) * tanhf(gc);
            h2s[t2] = sigf(go) * tanhf(c);
        }
        __syncthreads();

        // ---- classifier (tid<256, pair k-split over 116 (row,v) pairs) ----
        if (tid < 256) {
            int p = tid >> 1;
            bool valid = p < RR * VV;
            int pc = valid ? p : 0;
            int row = pc / VV, v = pc - row * VV;
            const u64* hp = (const u64*)&h2s[row * HH] + half * 16;
            u64 a = 0ull;
#pragma unroll
            for (int q = 0; q < 16; q++)
                a = ffma2(clsP[(half * 16 + q) * 32 + v], hp[q], a);
            float s = f2sum(a) + (half ? 0.0f : clsb[v]);
            s += __shfl_xor_sync(0xffffffffu, s, 1);
            if (valid && !half) {
                ps[row * 32 + v] = s;
                out[((size_t)step * BB + r0 + row) * VV + v] = s;
            }
        }
        __syncthreads();

        // ---- argmax (warp 0) + global release for step+1 ----
        if (tid < 32) {
            int row = tid >> 3, sl = tid & 7;
            float4 vv = *(const float4*)&ps[row * 32 + sl * 4];
            float best = vv.x; int bi = sl * 4;
            if (vv.y > best) { best = vv.y; bi = sl * 4 + 1; }
            if (vv.z > best) { best = vv.z; bi = sl * 4 + 2; }
            if (vv.w > best) { best = vv.w; bi = sl * 4 + 3; }
#pragma unroll
            for (int off = 1; off <= 4; off <<= 1) {
                float ob = __shfl_xor_sync(0xffffffffu, best, off);
                int   oi = __shfl_xor_sync(0xffffffffu, bi,   off);
                if (ob > best || (ob == best && oi < bi)) { best = ob; bi = oi; }
            }
            unsigned bits = (sl == 0) ? (1u << bi) : 0u;
            bits |= __shfl_xor_sync(0xffffffffu, bits, 8);
            bits |= __shfl_xor_sync(0xffffffffu, bits, 16);
            if (tid == 0) {
                atomicOr(&g_mask[step + 1], bits);
                __threadfence();
                atomicAdd(&g_cnt[step + 1], 1u);
            }
        }
        // no trailing sync: next pre-phase only READS h2s (next write to any
        // shared buffer is g1s, which is behind this step's syncs)
    }
}

// ---------------------------------------------------------------------------
// Launch
// ---------------------------------------------------------------------------
extern "C" void kernel_launch(void* const* d_in, const int* in_sizes, int n_in,
                              void* d_out, int out_size)
{
    const float* input_seq = (const float*)d_in[0];
    const float* enc_Wih0  = (const float*)d_in[1];
    const float* enc_Whh0  = (const float*)d_in[2];
    const float* enc_bih0  = (const float*)d_in[3];
    const float* enc_bhh0  = (const float*)d_in[4];
    const float* enc_Wih1  = (const float*)d_in[5];
    const float* enc_Whh1  = (const float*)d_in[6];
    const float* enc_bih1  = (const float*)d_in[7];
    const float* enc_bhh1  = (const float*)d_in[8];
    const float* d1_Wih    = (const float*)d_in[9];
    const float* d1_Whh    = (const float*)d_in[10];
    const float* d1_bih    = (const float*)d_in[11];
    const float* d1_bhh    = (const float*)d_in[12];
    const float* d2_Wih    = (const float*)d_in[13];
    const float* d2_Whh    = (const float*)d_in[14];
    const float* d2_bih    = (const float*)d_in[15];
    const float* d2_bhh    = (const float*)d_in[16];
    const float* cls_W     = (const float*)d_in[17];
    const float* cls_b     = (const float*)d_in[18];
    float* out = (float*)d_out;

    init_kernel<<<3, 512>>>();
    enc0_kernel<<<NBLK, 512>>>(input_seq, enc_Wih0, enc_Whh0, enc_bih0, enc_bhh0);
    enc1_kernel<<<NBLK, 512>>>(enc_Wih1, enc_Whh1, enc_bih1, enc_bhh1);
    dec_kernel<<<NBLK, 512>>>(d1_Wih, d1_Whh, d1_bih, d1_bhh,
                              d2_Wih, d2_Whh, d2_bih, d2_bhh,
                              cls_W, cls_b, out);
}